// round 16
// baseline (speedup 1.0000x reference)
#include <cuda_runtime.h>
#include <cuda_bf16.h>
#include <math.h>
#include <stdint.h>

#define T_TOK 8192
#define D_DIM 1024
#define H_DIM 4096
#define E_NUM 8
#define NSLOT (T_TOK * 2)

// ---------------------------------------------------------------------------
// Static device scratch
// ---------------------------------------------------------------------------
__device__ int   g_bad;               // 1 => FFMA fallback path
__device__ int   g_cnt[E_NUM];
__device__ int   g_off[E_NUM];
__device__ int   g_perm[E_NUM * T_TOK];
__device__ int   g_te[NSLOT];
__device__ int   g_tp[NSLOT];
__device__ float g_tw[NSLOT];
__device__ __align__(256) float g_h[(size_t)NSLOT * H_DIM];   // hidden fp32
__device__ __align__(256) float g_y[(size_t)NSLOT * D_DIM];   // per-slot out

// ---------------------------------------------------------------------------
#define MMA16816(c, a, b0, b1) \
    asm volatile("mma.sync.aligned.m16n8k16.row.col.f32.bf16.bf16.f32 " \
        "{%0,%1,%2,%3}, {%4,%5,%6,%7}, {%8,%9}, {%0,%1,%2,%3};" \
        : "+f"((c)[0]), "+f"((c)[1]), "+f"((c)[2]), "+f"((c)[3]) \
        : "r"((a)[0]), "r"((a)[1]), "r"((a)[2]), "r"((a)[3]), "r"(b0), "r"(b1))

__device__ __forceinline__ uint32_t pk2(__nv_bfloat16 a, __nv_bfloat16 b) {
    __nv_bfloat162 t; t.x = a; t.y = b;
    return *(uint32_t*)&t;
}

// Permuted-k byte positions.
// A row (96B stride, hi/lo separate): pair kp of group g at
//   g*32 + (kp&3)*8 + (kp>>2)*4      (+ (k&1)*2 within the pair)
// B row (192B stride, hi/lo interleaved 16B blocks): pair kp of group g:
//   hi at g*64 + (kp&3)*16 + (kp>>2)*4,  lo at +8.
__device__ __forceinline__ uint32_t a_pos(int k) {
    int g = k >> 4, kk = k & 15, kp = kk >> 1;
    return (uint32_t)(g * 32 + (kp & 3) * 8 + ((kp >> 2) & 1) * 4 + (k & 1) * 2);
}
__device__ __forceinline__ uint32_t b_pos_hi(int k) {
    int g = k >> 4, kk = k & 15, kp = kk >> 1;
    return (uint32_t)(g * 64 + (kp & 3) * 16 + ((kp >> 2) & 1) * 4 + (k & 1) * 2);
}

// ---------------------------------------------------------------------------
// K0: init counters + flag; warp 1 probes mma.sync + the EXACT permuted
// layout + wide fragment loads used by the GEMM.
// ---------------------------------------------------------------------------
__global__ void k_init_probe() {
    __shared__ __align__(16) char ps[16 * 96 * 2 + 8 * 192];   // AHI, ALO, B
    const int PALO = 1536, PB = 3072;
    int tid = threadIdx.x;
    if (tid < E_NUM) g_cnt[tid] = 0;
    if (tid == 0) g_bad = 0;
    __syncthreads();
    if (tid < 32 || tid >= 64) return;
    int lane = tid & 31;
    // Fill A (16 rows x 32 k) and B (8 rows x 32 k) from fp32 with hi/lo split
    for (int i = lane; i < 16 * 32; i += 32) {
        int r = i >> 5, k = i & 31;
        float v = 0.031f * (float)((r * 37 + k * 7) % 41) - 0.6f;
        __nv_bfloat16 hb = __float2bfloat16(v);
        *(__nv_bfloat16*)(ps + r * 96 + a_pos(k)) = hb;
        *(__nv_bfloat16*)(ps + PALO + r * 96 + a_pos(k)) =
            __float2bfloat16(v - __bfloat162float(hb));
    }
    for (int i = lane; i < 8 * 32; i += 32) {
        int n = i >> 5, k = i & 31;
        float v = 0.027f * (float)((n * 53 + k * 11) % 37) - 0.5f;
        __nv_bfloat16 hb = __float2bfloat16(v);
        *(__nv_bfloat16*)(ps + PB + n * 192 + b_pos_hi(k)) = hb;
        *(__nv_bfloat16*)(ps + PB + n * 192 + b_pos_hi(k) + 8) =
            __float2bfloat16(v - __bfloat162float(hb));
    }
    __syncwarp();
    int l4 = lane >> 2, l3 = lane & 3;
    float c[4] = {0.f, 0.f, 0.f, 0.f};
#pragma unroll
    for (int ks = 0; ks < 2; ks++) {
        uint32_t af[4], al[4];
        uint2 q0 = *(const uint2*)(ps + l4 * 96 + ks * 32 + l3 * 8);
        uint2 q1 = *(const uint2*)(ps + (l4 + 8) * 96 + ks * 32 + l3 * 8);
        af[0] = q0.x; af[1] = q1.x; af[2] = q0.y; af[3] = q1.y;
        uint2 p0 = *(const uint2*)(ps + PALO + l4 * 96 + ks * 32 + l3 * 8);
        uint2 p1 = *(const uint2*)(ps + PALO + (l4 + 8) * 96 + ks * 32 + l3 * 8);
        al[0] = p0.x; al[1] = p1.x; al[2] = p0.y; al[3] = p1.y;
        uint4 bb = *(const uint4*)(ps + PB + l4 * 192 + ks * 64 + l3 * 16);
        MMA16816(c, af, bb.x, bb.y);
        MMA16816(c, af, bb.z, bb.w);
        MMA16816(c, al, bb.x, bb.y);
    }
#pragma unroll
    for (int q = 0; q < 4; q++) {
        int r  = (lane >> 2) + ((q >= 2) ? 8 : 0);
        int cc = (lane & 3) * 2 + (q & 1);
        float ref = 0.0f;
        for (int k = 0; k < 32; k++) {
            float av = 0.031f * (float)((r * 37 + k * 7) % 41) - 0.6f;
            float bv = 0.027f * (float)((cc * 53 + k * 11) % 37) - 0.5f;
            __nv_bfloat16 ah = __float2bfloat16(av);
            __nv_bfloat16 bh = __float2bfloat16(bv);
            float ahf = __bfloat162float(ah), bhf = __bfloat162float(bh);
            float alf = __bfloat162float(__float2bfloat16(av - ahf));
            float blf = __bfloat162float(__float2bfloat16(bv - bhf));
            ref += ahf * bhf + ahf * blf + alf * bhf;
        }
        if (fabsf(c[q] - ref) > 1e-2f) atomicExch(&g_bad, 1);
    }
}

// ---------------------------------------------------------------------------
// Gating (proven)
// ---------------------------------------------------------------------------
__global__ void k_gate(const float* __restrict__ x,
                       const float* __restrict__ gw,
                       const float* __restrict__ gb) {
    int warp = (blockIdx.x * blockDim.x + threadIdx.x) >> 5;
    int lane = threadIdx.x & 31;
    if (warp >= T_TOK) return;
    const float* xr = x + (size_t)warp * D_DIM;
    float acc[E_NUM];
#pragma unroll
    for (int e = 0; e < E_NUM; e++) acc[e] = 0.0f;
    for (int d = lane; d < D_DIM; d += 32) {
        float xv = xr[d];
        const float* g = gw + d * E_NUM;
#pragma unroll
        for (int e = 0; e < E_NUM; e++) acc[e] += xv * g[e];
    }
#pragma unroll
    for (int e = 0; e < E_NUM; e++)
#pragma unroll
        for (int o = 16; o > 0; o >>= 1)
            acc[e] += __shfl_xor_sync(0xFFFFFFFFu, acc[e], o);
    if (lane == 0) {
        float best = -1e30f, sec = -1e30f;
        int bi = 0, si = 0;
#pragma unroll
        for (int e = 0; e < E_NUM; e++) {
            float v = acc[e] + gb[e];
            if (v > best) { sec = best; si = bi; best = v; bi = e; }
            else if (v > sec) { sec = v; si = e; }
        }
        float g1 = 1.0f / (1.0f + expf(best - sec));
        float g0 = 1.0f - g1;
        int p0 = atomicAdd(&g_cnt[bi], 1);
        g_perm[bi * T_TOK + p0] = warp;
        g_te[2 * warp] = bi; g_tp[2 * warp] = p0; g_tw[2 * warp] = g0;
        int p1 = atomicAdd(&g_cnt[si], 1);
        g_perm[si * T_TOK + p1] = warp;
        g_te[2 * warp + 1] = si; g_tp[2 * warp + 1] = p1; g_tw[2 * warp + 1] = g1;
    }
}

__global__ void k_off() {
    if (threadIdx.x == 0) {
        int s = 0;
#pragma unroll
        for (int e = 0; e < E_NUM; e++) { g_off[e] = s; s += g_cnt[e]; }
    }
}

// ---------------------------------------------------------------------------
// smem layout per 48KB stage:
//   AHI @ 0      : 128 rows x 96B (permuted-k)
//   ALO @ 12288  : 128 rows x 96B
//   B   @ 24576  : 128 rows x 192B (hi/lo interleaved 16B blocks, permuted-k)
// ---------------------------------------------------------------------------
#define S_ALO 12288
#define S_B   24576
#define STG_B 49152

#define GFETCH(c) do { \
    _Pragma("unroll") \
    for (int j = 0; j < 4; j++) { \
        float4 f = *(const float4*)(aSrc + (size_t)(c) * 32 + j * 4); \
        __nv_bfloat16 hx = __float2bfloat16(f.x), hy = __float2bfloat16(f.y); \
        __nv_bfloat16 hz = __float2bfloat16(f.z), hw = __float2bfloat16(f.w); \
        aH2[j].x = pk2(hx, hy); aH2[j].y = pk2(hz, hw); \
        aL2[j].x = pk2(__float2bfloat16(f.x - __bfloat162float(hx)), \
                       __float2bfloat16(f.y - __bfloat162float(hy))); \
        aL2[j].y = pk2(__float2bfloat16(f.z - __bfloat162float(hz)), \
                       __float2bfloat16(f.w - __bfloat162float(hw))); \
    } \
    _Pragma("unroll") \
    for (int q = 0; q < 4; q++) { \
        _Pragma("unroll") \
        for (int r = 0; r < 2; r++) { \
            const float* p = bSrc + (size_t)((c) * 32 + 2 * bl3 + 8 * q) * Nd + 8 * r; \
            float f0 = p[0], f1 = p[Nd]; \
            __nv_bfloat16 h0 = __float2bfloat16(f0), h1 = __float2bfloat16(f1); \
            bH[q * 2 + r] = pk2(h0, h1); \
            bL[q * 2 + r] = pk2(__float2bfloat16(f0 - __bfloat162float(h0)), \
                                __float2bfloat16(f1 - __bfloat162float(h1))); \
        } \
    } } while (0)

// A: thread (ar, axc=g) stores its 8 pairs (slot j = pair index, compile-time
// data select) at permuted positions. B: thread stores 8 (q,r) pairs into the
// interleaved blocks.
#define GSTORE(sbase) do { \
    char* s_ = (sbase); \
    _Pragma("unroll") \
    for (int j = 0; j < 8; j++) { \
        uint32_t ad = aDst + (uint32_t)(axc * 32 + (j & 3) * 8 + (j >> 2) * 4); \
        uint32_t hv = (j & 1) ? aH2[j >> 1].y : aH2[j >> 1].x; \
        uint32_t lv = (j & 1) ? aL2[j >> 1].y : aL2[j >> 1].x; \
        *(uint32_t*)(s_ + ad) = hv; \
        *(uint32_t*)(s_ + S_ALO + ad) = lv; \
    } \
    _Pragma("unroll") \
    for (int i = 0; i < 8; i++) { \
        int q_ = i >> 1, r_ = i & 1; \
        uint32_t bd = bDst + (uint32_t)(r_ * 1536 + (q_ >> 1) * 64 + (q_ & 1) * 4); \
        *(uint32_t*)(s_ + S_B + bd) = bH[q_ * 2 + r_]; \
        *(uint32_t*)(s_ + S_B + bd + 8) = bL[q_ * 2 + r_]; \
    } } while (0)

#define GCOMPUTE(sbase) do { \
    char* base = (sbase); \
    _Pragma("unroll") \
    for (int ks = 0; ks < 2; ks++) { \
        uint32_t af[4][4]; \
        _Pragma("unroll") \
        for (int mt = 0; mt < 4; mt++) { \
            int rb = (wm * 64 + mt * 16 + l4) * 96 + ks * 32 + l3 * 8; \
            uint2 q0 = *(const uint2*)(base + rb); \
            uint2 q1 = *(const uint2*)(base + rb + 768); \
            af[mt][0] = q0.x; af[mt][1] = q1.x; af[mt][2] = q0.y; af[mt][3] = q1.y; \
        } \
        _Pragma("unroll") \
        for (int o = 0; o < 4; o++) { \
            uint4 bb = *(const uint4*)(base + S_B + \
                (wn * 32 + o * 8 + l4) * 192 + ks * 64 + l3 * 16); \
            _Pragma("unroll") \
            for (int mt = 0; mt < 4; mt++) MMA16816(acc[mt][o], af[mt], bb.x, bb.y); \
            _Pragma("unroll") \
            for (int mt = 0; mt < 4; mt++) MMA16816(acc[mt][o], af[mt], bb.z, bb.w); \
        } \
        _Pragma("unroll") \
        for (int mt = 0; mt < 4; mt++) { \
            int rb = S_ALO + (wm * 64 + mt * 16 + l4) * 96 + ks * 32 + l3 * 8; \
            uint2 q0 = *(const uint2*)(base + rb); \
            uint2 q1 = *(const uint2*)(base + rb + 768); \
            af[mt][0] = q0.x; af[mt][1] = q1.x; af[mt][2] = q0.y; af[mt][3] = q1.y; \
        } \
        _Pragma("unroll") \
        for (int o = 0; o < 4; o++) { \
            uint4 bb = *(const uint4*)(base + S_B + \
                (wn * 32 + o * 8 + l4) * 192 + ks * 64 + l3 * 16); \
            _Pragma("unroll") \
            for (int mt = 0; mt < 4; mt++) MMA16816(acc[mt][o], af[mt], bb.x, bb.y); \
        } \
    } } while (0)

#define GEPILOGUE() do { \
    _Pragma("unroll") \
    for (int mt = 0; mt < 4; mt++) { \
        _Pragma("unroll") \
        for (int rr = 0; rr < 2; rr++) { \
            int r = m0 + wm * 64 + mt * 16 + (lane >> 2) + rr * 8; \
            if (r >= cnt) continue; \
            if (IS1) { \
                const float* be = bias + (size_t)e * Nd + n0; \
                float* hr = g_h + (size_t)(off + r) * H_DIM + n0; \
                _Pragma("unroll") \
                for (int o = 0; o < 4; o++) { \
                    int col = wn * 32 + o * 8 + (lane & 3) * 2; \
                    float v0 = acc[mt][o][rr * 2 + 0] + be[col]; \
                    float v1 = acc[mt][o][rr * 2 + 1] + be[col + 1]; \
                    v0 = 0.5f * v0 * (1.0f + erff(v0 * 0.70710678118654752f)); \
                    v1 = 0.5f * v1 * (1.0f + erff(v1 * 0.70710678118654752f)); \
                    float2 v; v.x = v0; v.y = v1; \
                    *(float2*)(hr + col) = v; \
                } \
            } else { \
                float* yr = g_y + (size_t)(off + r) * D_DIM + n0; \
                _Pragma("unroll") \
                for (int o = 0; o < 4; o++) { \
                    int col = wn * 32 + o * 8 + (lane & 3) * 2; \
                    float2 v; \
                    v.x = acc[mt][o][rr * 2 + 0]; \
                    v.y = acc[mt][o][rr * 2 + 1]; \
                    *(float2*)(yr + col) = v; \
                } \
            } \
        } \
    } } while (0)

#define GPROLOG() \
    int e = blockIdx.z; \
    int cnt = g_cnt[e]; \
    int m0 = blockIdx.y * 128; \
    if (m0 >= cnt) return; \
    int n0 = blockIdx.x * 128; \
    int off = g_off[e]; \
    int tid = threadIdx.x, lane = tid & 31, wid = tid >> 5; \
    int wm = wid >> 2, wn = wid & 3; \
    int ar = tid >> 1, axc = tid & 1; \
    int mrow = m0 + ar; if (mrow > cnt - 1) mrow = cnt - 1; \
    const float* aSrc; \
    if (IS1) { \
        int tok = g_perm[e * T_TOK + mrow]; \
        aSrc = x + (size_t)tok * Kd; \
    } else { \
        aSrc = g_h + (size_t)(off + mrow) * Kd; \
    } \
    aSrc += axc * 16; \
    uint32_t aDst = (uint32_t)(ar * 96); \
    int bl4 = lane >> 2, bl3 = lane & 3; \
    const float* bSrc = w + (size_t)e * Kd * Nd + (n0 + wid * 16 + bl4); \
    uint32_t bDst = (uint32_t)((wid * 16 + bl4) * 192 + bl3 * 16); \
    uint2    aH2[4], aL2[4]; \
    uint32_t bH[8], bL[8]; \
    float acc[4][4][4]; \
    _Pragma("unroll") \
    for (int i = 0; i < 4; i++) \
        _Pragma("unroll") \
        for (int j = 0; j < 4; j++) \
            _Pragma("unroll") \
            for (int q = 0; q < 4; q++) acc[i][j][q] = 0.0f; \
    const int NC = Kd / 32; \
    int l4 = lane >> 2; \
    int l3 = lane & 3;

// ---------------------------------------------------------------------------
// Variant A: double-buffered, 96KB dynamic smem, 1 sync/chunk.
// ---------------------------------------------------------------------------
template<int Nd, int Kd, bool IS1>
__global__ __launch_bounds__(256, 2)
void k_gemm_b(const float* __restrict__ x,
              const float* __restrict__ w,
              const float* __restrict__ bias) {
    if (g_bad) return;
    extern __shared__ __align__(16) char smx[];
    GPROLOG();

    GFETCH(0);
    GSTORE(smx);
    if (NC > 1) GFETCH(1);
    __syncthreads();

    for (int c = 0; c < NC; c++) {
        if (c + 1 < NC) GSTORE(smx + ((c + 1) & 1) * STG_B);
        if (c + 2 < NC) GFETCH(c + 2);
        GCOMPUTE(smx + (c & 1) * STG_B);
        __syncthreads();
    }
    GEPILOGUE();
}

// ---------------------------------------------------------------------------
// Variant B: single 48KB static buffer (if big-smem opt-in fails).
// ---------------------------------------------------------------------------
template<int Nd, int Kd, bool IS1>
__global__ __launch_bounds__(256, 2)
void k_gemm_s(const float* __restrict__ x,
              const float* __restrict__ w,
              const float* __restrict__ bias) {
    if (g_bad) return;
    __shared__ __align__(16) char sms[STG_B];
    GPROLOG();

    GFETCH(0);
    for (int c = 0; c < NC; c++) {
        __syncthreads();
        GSTORE(sms);
        __syncthreads();
        if (c + 1 < NC) GFETCH(c + 1);
        GCOMPUTE(sms);
    }
    GEPILOGUE();
}

// ---------------------------------------------------------------------------
// Combine (mma path)
// ---------------------------------------------------------------------------
__global__ void k_combine(const float* __restrict__ b2, float* __restrict__ out) {
    if (g_bad) return;
    int t = blockIdx.x;
    int d = threadIdx.x * 4;
    int e0 = g_te[2 * t], e1 = g_te[2 * t + 1];
    float w0 = g_tw[2 * t], w1 = g_tw[2 * t + 1];
    size_t s0 = (size_t)(g_off[e0] + g_tp[2 * t]) * D_DIM;
    size_t s1 = (size_t)(g_off[e1] + g_tp[2 * t + 1]) * D_DIM;
    float4 y0 = *(const float4*)(g_y + s0 + d);
    float4 y1 = *(const float4*)(g_y + s1 + d);
    float4 c0 = *(const float4*)(b2 + (size_t)e0 * D_DIM + d);
    float4 c1 = *(const float4*)(b2 + (size_t)e1 * D_DIM + d);
    float4 o;
    o.x = w0 * (y0.x + c0.x) + w1 * (y1.x + c1.x);
    o.y = w0 * (y0.y + c0.y) + w1 * (y1.y + c1.y);
    o.z = w0 * (y0.z + c0.z) + w1 * (y1.z + c1.z);
    o.w = w0 * (y0.w + c0.w) + w1 * (y1.w + c1.w);
    *(float4*)(out + (size_t)t * D_DIM + d) = o;
}

// ===========================================================================
// FALLBACK PATH (g_bad==1): FFMA pipeline, fp32 hidden in g_h
// ===========================================================================
__global__ void k_zero(float* __restrict__ out, int n) {
    if (!g_bad) return;
    int i = blockIdx.x * blockDim.x + threadIdx.x;
    int stride = gridDim.x * blockDim.x;
    for (; i < n; i += stride) out[i] = 0.0f;
}

__global__ __launch_bounds__(256)
void k_g1f(const float* __restrict__ x,
           const float* __restrict__ w1,
           const float* __restrict__ b1) {
    if (!g_bad) return;
    int e   = blockIdx.z;
    int cnt = g_cnt[e];
    int m0  = blockIdx.y * 128;
    if (m0 >= cnt) return;
    int n0  = blockIdx.x * 128;

    __shared__ float As[8][128];
    __shared__ float Bs[8][128];

    int tid = threadIdx.x;
    int am = tid >> 1;
    int ak = (tid & 1) * 4;
    int tok = -1;
    if (m0 + am < cnt) tok = g_perm[e * T_TOK + m0 + am];
    int bk = tid >> 5;
    int bn = (tid & 31) * 4;
    const float* w1e = w1 + (size_t)e * D_DIM * H_DIM;

    int tx = tid & 15, ty = tid >> 4;
    float acc[8][8];
#pragma unroll
    for (int i = 0; i < 8; i++)
#pragma unroll
        for (int j = 0; j < 8; j++) acc[i][j] = 0.0f;

    for (int k0 = 0; k0 < D_DIM; k0 += 8) {
        float4 av = make_float4(0.f, 0.f, 0.f, 0.f);
        if (tok >= 0) av = *(const float4*)(x + (size_t)tok * D_DIM + k0 + ak);
        float4 bv = *(const float4*)(w1e + (size_t)(k0 + bk) * H_DIM + n0 + bn);
        __syncthreads();
        As[ak + 0][am] = av.x; As[ak + 1][am] = av.y;
        As[ak + 2][am] = av.z; As[ak + 3][am] = av.w;
        *(float4*)&Bs[bk][bn] = bv;
        __syncthreads();
#pragma unroll
        for (int k = 0; k < 8; k++) {
            float a[8], b[8];
            *(float4*)(a)     = *(float4*)&As[k][ty * 4];
            *(float4*)(a + 4) = *(float4*)&As[k][64 + ty * 4];
            *(float4*)(b)     = *(float4*)&Bs[k][tx * 4];
            *(float4*)(b + 4) = *(float4*)&Bs[k][64 + tx * 4];
#pragma unroll
            for (int i = 0; i < 8; i++)
#pragma unroll
                for (int j = 0; j < 8; j++) acc[i][j] += a[i] * b[j];
        }
    }

    int off = g_off[e];
    const float* b1e = b1 + (size_t)e * H_DIM;
#pragma unroll
    for (int i = 0; i < 8; i++) {
        int rm = (i < 4) ? (ty * 4 + i) : (64 + ty * 4 + (i - 4));
        int m = m0 + rm;
        if (m >= cnt) continue;
        float* hrow = g_h + (size_t)(off + m) * H_DIM;
#pragma unroll
        for (int j = 0; j < 8; j++) {
            int rn = (j < 4) ? (tx * 4 + j) : (64 + tx * 4 + (j - 4));
            int n = n0 + rn;
            float h = acc[i][j] + b1e[n];
            h = 0.5f * h * (1.0f + erff(h * 0.70710678118654752f));
            hrow[n] = h;
        }
    }
}

__global__ __launch_bounds__(256)
void k_g2f(const float* __restrict__ w2,
           const float* __restrict__ b2,
           float* __restrict__ out) {
    if (!g_bad) return;
    int e   = blockIdx.z;
    int cnt = g_cnt[e];
    int m0  = blockIdx.y * 128;
    if (m0 >= cnt) return;
    int n0  = blockIdx.x * 128;
    int off = g_off[e];

    __shared__ float As[8][128];
    __shared__ float Bs[8][128];

    int tid = threadIdx.x;
    int am = tid >> 1;
    int ak = (tid & 1) * 4;
    bool avalid = (m0 + am < cnt);
    const float* arow = g_h + (size_t)(off + m0 + (avalid ? am : 0)) * H_DIM;
    int bk = tid >> 5;
    int bn = (tid & 31) * 4;
    const float* w2e = w2 + (size_t)e * H_DIM * D_DIM;

    int tx = tid & 15, ty = tid >> 4;
    float acc[8][8];
#pragma unroll
    for (int i = 0; i < 8; i++)
#pragma unroll
        for (int j = 0; j < 8; j++) acc[i][j] = 0.0f;

    for (int k0 = 0; k0 < H_DIM; k0 += 8) {
        float4 av = make_float4(0.f, 0.f, 0.f, 0.f);
        if (avalid) av = *(const float4*)(arow + k0 + ak);
        float4 bv = *(const float4*)(w2e + (size_t)(k0 + bk) * D_DIM + n0 + bn);
        __syncthreads();
        As[ak + 0][am] = av.x; As[ak + 1][am] = av.y;
        As[ak + 2][am] = av.z; As[ak + 3][am] = av.w;
        *(float4*)&Bs[bk][bn] = bv;
        __syncthreads();
#pragma unroll
        for (int k = 0; k < 8; k++) {
            float a[8], b[8];
            *(float4*)(a)     = *(float4*)&As[k][ty * 4];
            *(float4*)(a + 4) = *(float4*)&As[k][64 + ty * 4];
            *(float4*)(b)     = *(float4*)&Bs[k][tx * 4];
            *(float4*)(b + 4) = *(float4*)&Bs[k][64 + tx * 4];
#pragma unroll
            for (int i = 0; i < 8; i++)
#pragma unroll
                for (int j = 0; j < 8; j++) acc[i][j] += a[i] * b[j];
        }
    }

    const float* b2e = b2 + (size_t)e * D_DIM;
#pragma unroll
    for (int i = 0; i < 8; i++) {
        int rm = (i < 4) ? (ty * 4 + i) : (64 + ty * 4 + (i - 4));
        int m = m0 + rm;
        if (m >= cnt) continue;
        int   tok = g_perm[e * T_TOK + m];
        float w0 = g_tw[2 * tok], w1v = g_tw[2 * tok + 1];
        float w = (g_te[2 * tok] == e) ? w0 : w1v;
        float* orow = out + (size_t)tok * D_DIM;
#pragma unroll
        for (int j = 0; j < 8; j++) {
            int rn = (j < 4) ? (tx * 4 + j) : (64 + tx * 4 + (j - 4));
            int n = n0 + rn;
            float y = acc[i][j] + b2e[n];
            atomicAdd(&orow[n], w * y);
        }
    }
}

// ---------------------------------------------------------------------------
// Launch (k_gemm1 at app-launch index 3 for ncu)
// ---------------------------------------------------------------------------
extern "C" void kernel_launch(void* const* d_in, const int* in_sizes, int n_in,
                              void* d_out, int out_size) {
    const float* x  = (const float*)d_in[0];
    const float* gw = (const float*)d_in[1];
    const float* gb = (const float*)d_in[2];
    const float* w1 = (const float*)d_in[3];
    const float* b1 = (const float*)d_in[4];
    const float* w2 = (const float*)d_in[5];
    const float* b2 = (const float*)d_in[6];
    float* out = (float*)d_out;
    (void)in_sizes; (void)n_in;

    cudaError_t ea = cudaFuncSetAttribute(k_gemm_b<H_DIM, D_DIM, true>,
                        cudaFuncAttributeMaxDynamicSharedMemorySize, 2 * STG_B);
    cudaError_t eb = cudaFuncSetAttribute(k_gemm_b<D_DIM, H_DIM, false>,
                        cudaFuncAttributeMaxDynamicSharedMemorySize, 2 * STG_B);
    bool big = (ea == cudaSuccess) && (eb == cudaSuccess);

    k_init_probe<<<1, 64>>>();                                         // 0
    k_gate<<<(T_TOK * 32 + 255) / 256, 256>>>(x, gw, gb);              // 1
    k_off<<<1, 32>>>();                                                // 2
    if (big) {
        k_gemm_b<H_DIM, D_DIM, true>                                   // 3 <- ncu
            <<<dim3(H_DIM / 128, T_TOK / 128, E_NUM), 256, 2 * STG_B>>>(x, w1, b1);
        k_gemm_b<D_DIM, H_DIM, false>                                  // 4
            <<<dim3(D_DIM / 128, T_TOK / 128, E_NUM), 256, 2 * STG_B>>>(x, w2, b2);
    } else {
        k_gemm_s<H_DIM, D_DIM, true>
            <<<dim3(H_DIM / 128, T_TOK / 128, E_NUM), 256>>>(x, w1, b1);
        k_gemm_s<D_DIM, H_DIM, false>
            <<<dim3(D_DIM / 128, T_TOK / 128, E_NUM), 256>>>(x, w2, b2);
    }
    k_combine<<<T_TOK, 256>>>(b2, out);                                // 5
    k_zero<<<2048, 256>>>(out, out_size);                              // 6
    k_g1f<<<dim3(H_DIM / 128, T_TOK / 128, E_NUM), 256>>>(x, w1, b1);  // 7
    k_g2f<<<dim3(D_DIM / 128, T_TOK / 128, E_NUM), 256>>>(w2, b2, out);// 8
}